// round 5
// baseline (speedup 1.0000x reference)
#include <cuda_runtime.h>
#include <mma.h>
#include <cstdint>
#include <cstddef>

using namespace nvcuda;

// Problem dims (fixed by the dataset)
#define B_ROWS 65536
#define C_DIM  512
#define K_DIM  512

// ---------------- GEMM tiling ----------------
constexpr int BM = 128;          // block tile M
constexpr int BN = 64;           // block tile N
constexpr int BK = 16;           // block tile K (small -> 3 stages fit in 48KB static)
constexpr int PAD = 4;
constexpr int LDS_T = BK + PAD;  // 20 floats row stride (multiple of 4 -> valid wmma ldm)
constexpr int A_FLOATS   = BM * LDS_T;              // 2560
constexpr int B_OFF      = A_FLOATS;                // B tile after A tile within a stage
constexpr int STAGE_FLTS = (BM + BN) * LDS_T;       // 3840 floats = 15360 B
constexpr int NSTAGE     = 3;
constexpr int AUX_OFF    = NSTAGE * STAGE_FLTS;     // 11520
constexpr int SMEM_FLOATS = AUX_OFF + 3 * BN;       // 11712 floats = 46848 B (STATIC, <48KB)
constexpr int LDC = BN + 4;                          // 68 (epilogue parking, reuses stage mem)
constexpr int NT  = K_DIM / BK;                      // 32 k-tiles

// ---------------- EMA scan config ----------------
constexpr int EMA_CHUNK  = 128;
constexpr int EMA_WARMUP = 512;   // 0.95^512 ~ 4e-12 << fp32 ulp -> truncation is exact

// ============================================================
// cp.async helpers (16B, L2-cached)
// ============================================================
__device__ __forceinline__ void cp_async16(void* smem_dst, const void* gmem_src) {
    uint32_t s = (uint32_t)__cvta_generic_to_shared(smem_dst);
    asm volatile("cp.async.cg.shared.global [%0], [%1], 16;\n" :: "r"(s), "l"(gmem_src));
}
__device__ __forceinline__ void cp_commit() {
    asm volatile("cp.async.commit_group;\n");
}
template <int N>
__device__ __forceinline__ void cp_wait() {
    asm volatile("cp.async.wait_group %0;\n" :: "n"(N));
}

// ============================================================
// Kernel 1: init wager output with bias.
// Runs every replay: the GEMM accumulates into wager with atomics, so the
// buffer is re-seeded each graph replay for determinism.
// ============================================================
__global__ void init_wager_kernel(float* __restrict__ wager,
                                  const float* __restrict__ b_wager)
{
    int i = blockIdx.x * blockDim.x + threadIdx.x;
    if (i < B_ROWS) {
        float2 v = make_float2(b_wager[0], b_wager[1]);
        reinterpret_cast<float2*>(wager)[i] = v;
    }
}

// ============================================================
// Kernel 2: EMA target via warmup-truncated parallel scan.
// ema_i = 0.05*g_i + 0.95*ema_{i-1};  greater = g_i > ema_i
// ============================================================
__global__ void ema_target_kernel(const float* __restrict__ rewards,
                                  float* __restrict__ target)
{
    int t = blockIdx.x * blockDim.x + threadIdx.x;   // 512 workers
    int start = t * EMA_CHUNK;
    if (start >= B_ROWS) return;
    int w0 = start - EMA_WARMUP;
    if (w0 < 0) w0 = 0;

    float ema = 0.0f;
    for (int i = w0; i < start; i++)
        ema = 0.05f * rewards[i] + 0.95f * ema;
    for (int i = start; i < start + EMA_CHUNK; i++) {
        float g = rewards[i];
        ema = 0.05f * g + 0.95f * ema;
        bool gt = g > ema;
        target[2 * i + 0] = gt ? 1.0f : 0.0f;
        target[2 * i + 1] = gt ? 0.0f : 1.0f;
    }
}

// ============================================================
// Kernel 3: fused tf32 GEMM (3-stage cp.async pipeline) + relu + cascade
// blend + wager GEMV epilogue.
//   Per k-tile: wait_group<1> -> barrier -> issue(kt+2) -> compute(kt).
//   Single barrier suffices: the reissued stage was consumed at kt-1, and
//   every thread's compute(kt-1) precedes its barrier at kt.
// tf32 round-to-nearest happens in fragment registers (raw fp32 staged),
// preserving the unbiased-rounding numerics that passed R2 at 2.8e-4.
// ============================================================
__global__ __launch_bounds__(256, 2)
void gemm_fused_kernel(const float* __restrict__ A,
                       const float* __restrict__ prev,
                       const float* __restrict__ cascade,
                       const float* __restrict__ W,
                       const float* __restrict__ bias,
                       const float* __restrict__ Wwag,
                       float* __restrict__ wager,
                       float* __restrict__ comp)
{
    __shared__ float smem[SMEM_FLOATS];

    const int t  = threadIdx.x;
    const int n0 = blockIdx.x * BN;   // n fastest -> A slab shared in L2
    const int m0 = blockIdx.y * BM;

    float* aux = smem + AUX_OFF;
    if (t < BN) {
        aux[t]            = bias[n0 + t];
        aux[BN + t]       = Wwag[n0 + t];            // W_wager row 0
        aux[2 * BN + t]   = Wwag[C_DIM + n0 + t];    // W_wager row 1
    }

    // -------- cp.async staging map: 3 x 16B per thread per stage --------
    const int lrow = t >> 2;   // 0..63
    const int lc4  = t & 3;    // 0..3 (float4 column within 16-float row)

    auto issue_stage = [&](int s, int kt) {
        float* st = smem + s * STAGE_FLTS;
        const float* Ag = A + (size_t)(m0 + lrow) * K_DIM + kt * BK + lc4 * 4;
#pragma unroll
        for (int p = 0; p < 2; p++) {
            int row = lrow + p * 64;
            cp_async16(st + row * LDS_T + lc4 * 4, Ag + (size_t)p * 64 * K_DIM);
        }
        cp_async16(st + B_OFF + lrow * LDS_T + lc4 * 4,
                   W + (size_t)(n0 + lrow) * K_DIM + kt * BK + lc4 * 4);
        cp_commit();
    };

    const int wid = t >> 5;
    const int wm  = wid & 3;    // 0..3 (M)
    const int wn  = wid >> 2;   // 0..1 (N)

    wmma::fragment<wmma::accumulator, 16, 16, 8, float> acc[2][2];
#pragma unroll
    for (int i = 0; i < 2; i++)
#pragma unroll
        for (int j = 0; j < 2; j++)
            wmma::fill_fragment(acc[i][j], 0.0f);

    // -------- prologue: stages 0,1 in flight --------
    issue_stage(0, 0);
    issue_stage(1, 1);

    // -------- mainloop --------
    for (int kt = 0; kt < NT; kt++) {
        cp_wait<NSTAGE - 2>();      // my groups for tiles <= kt done
        __syncthreads();            // everyone's tile kt visible; stage (kt-1)%3 free

        if (kt + 2 < NT) issue_stage((kt + 2) % NSTAGE, kt + 2);

        const float* As = smem + (kt % NSTAGE) * STAGE_FLTS;
        const float* Bs = As + B_OFF;

#pragma unroll
        for (int kk = 0; kk < BK / 8; kk++) {
            wmma::fragment<wmma::matrix_a, 16, 16, 8, wmma::precision::tf32, wmma::row_major> af[2];
            wmma::fragment<wmma::matrix_b, 16, 16, 8, wmma::precision::tf32, wmma::col_major> bf[2];
#pragma unroll
            for (int i = 0; i < 2; i++) {
                wmma::load_matrix_sync(af[i], As + (wm * 32 + i * 16) * LDS_T + kk * 8, LDS_T);
#pragma unroll
                for (int e = 0; e < af[i].num_elements; e++)
                    af[i].x[e] = wmma::__float_to_tf32(af[i].x[e]);   // round-to-nearest tf32
            }
#pragma unroll
            for (int j = 0; j < 2; j++) {
                wmma::load_matrix_sync(bf[j], Bs + (wn * 32 + j * 16) * LDS_T + kk * 8, LDS_T);
#pragma unroll
                for (int e = 0; e < bf[j].num_elements; e++)
                    bf[j].x[e] = wmma::__float_to_tf32(bf[j].x[e]);
            }
#pragma unroll
            for (int i = 0; i < 2; i++)
#pragma unroll
                for (int j = 0; j < 2; j++)
                    wmma::mma_sync(acc[i][j], af[i], bf[j], acc[i][j]);
        }
    }

    __syncthreads();   // all reads of stage memory done before Cs overwrites it

    // -------- epilogue: park C, then blend + store + wager GEMV --------
    float* Cs = smem;  // 128 x 68 floats = 34.8 KB, fits in stage region (46KB)
#pragma unroll
    for (int i = 0; i < 2; i++)
#pragma unroll
        for (int j = 0; j < 2; j++)
            wmma::store_matrix_sync(Cs + (wm * 32 + i * 16) * LDC + wn * 32 + j * 16,
                                    acc[i][j], LDC, wmma::mem_row_major);
    __syncthreads();

    const float r   = *cascade;
    const float omr = 1.0f - r;
    const int erow = t >> 4;        // 0..15
    const int ec   = (t & 15) * 4;  // 0,4,...,60

#pragma unroll
    for (int p = 0; p < 8; p++) {
        int row = erow + p * 16;
        int gm  = m0 + row;

        const float4 pv = *reinterpret_cast<const float4*>(
            prev + (size_t)gm * C_DIM + n0 + ec);

        float h0 = fmaxf(Cs[row * LDC + ec + 0] + aux[ec + 0], 0.0f);
        float h1 = fmaxf(Cs[row * LDC + ec + 1] + aux[ec + 1], 0.0f);
        float h2 = fmaxf(Cs[row * LDC + ec + 2] + aux[ec + 2], 0.0f);
        float h3 = fmaxf(Cs[row * LDC + ec + 3] + aux[ec + 3], 0.0f);

        float4 o;
        o.x = fmaf(r, h0, omr * pv.x);
        o.y = fmaf(r, h1, omr * pv.y);
        o.z = fmaf(r, h2, omr * pv.z);
        o.w = fmaf(r, h3, omr * pv.w);

        *reinterpret_cast<float4*>(comp + (size_t)gm * C_DIM + n0 + ec) = o;

        float w0 = o.x * aux[BN + ec + 0] + o.y * aux[BN + ec + 1]
                 + o.z * aux[BN + ec + 2] + o.w * aux[BN + ec + 3];
        float w1 = o.x * aux[2 * BN + ec + 0] + o.y * aux[2 * BN + ec + 1]
                 + o.z * aux[2 * BN + ec + 2] + o.w * aux[2 * BN + ec + 3];

#pragma unroll
        for (int off = 8; off; off >>= 1) {
            w0 += __shfl_xor_sync(0xffffffffu, w0, off);
            w1 += __shfl_xor_sync(0xffffffffu, w1, off);
        }
        if ((t & 15) == 0) {
            atomicAdd(wager + (size_t)gm * 2 + 0, w0);
            atomicAdd(wager + (size_t)gm * 2 + 1, w1);
        }
    }
}

// ============================================================
// Launch — nothing but three launches; no statics, no attributes, no allocs.
// Inputs (metadata order):
//  0 comparison_matrix [B,512] f32   1 prev_comparison [B,512] f32
//  2 cascade_rate [1] f32            3 rewards [B] f32
//  4 W_comp [512,512] f32            5 b_comp [512] f32
//  6 W_wager [2,512] f32             7 b_wager [2] f32
// Output: concat( wager [B,2], comparison_out [B,512], target [B,2] ) f32
// ============================================================
extern "C" void kernel_launch(void* const* d_in, const int* in_sizes, int n_in,
                              void* d_out, int out_size)
{
    const float* A    = (const float*)d_in[0];
    const float* prev = (const float*)d_in[1];
    const float* casc = (const float*)d_in[2];
    const float* rew  = (const float*)d_in[3];
    const float* W    = (const float*)d_in[4];
    const float* bc   = (const float*)d_in[5];
    const float* Ww   = (const float*)d_in[6];
    const float* bw   = (const float*)d_in[7];

    float* out    = (float*)d_out;
    float* wager  = out;                                                // [B,2]
    float* comp   = out + (size_t)B_ROWS * 2;                           // [B,512]
    float* target = out + (size_t)B_ROWS * 2 + (size_t)B_ROWS * C_DIM;  // [B,2]

    init_wager_kernel<<<(B_ROWS + 255) / 256, 256>>>(wager, bw);
    ema_target_kernel<<<4, 128>>>(rew, target);

    dim3 grid(C_DIM / BN, B_ROWS / BM);   // (8, 512); n fastest -> A slab L2 reuse
    gemm_fused_kernel<<<grid, 256>>>(A, prev, casc, W, bc, Ww, wager, comp);
}

// round 7
// speedup vs baseline: 1.0842x; 1.0842x over previous
#include <cuda_runtime.h>
#include <cstdint>
#include <cstddef>

// Problem dims (fixed by the dataset)
#define B_ROWS 65536
#define C_DIM  512
#define K_DIM  512

// ---------------- tiling ----------------
// grid = 512 blocks, each owns 128 rows x FULL N=512 (4 passes of 128 cols).
// block = 256 threads = 8 warps: wm in {0,1} (64 rows), wn in {0..3} (32 cols).
// warp tile 64x32 = 4 m-frags (m16) x 4 n-frags (n8), mma.m16n8k8.tf32.
constexpr int BK       = 16;                 // k-floats per tile
constexpr int LDS_R    = 20;                 // smem row stride in floats (20 % 8 == 4 -> conflict-free)
constexpr int STAGE_F  = 256 * LDS_R;        // 128 A-rows + 128 B-rows per stage = 5120 floats
constexpr int NSTAGE   = 2;
constexpr int AUX_OFF  = NSTAGE * STAGE_F;   // 10240
// aux: bias[512], wag0[512], wag1[512], wacc[256]
constexpr int SMEM_F   = AUX_OFF + 512 * 3 + 256;   // 12032 floats = 48128 B (static, <=48KB)
constexpr int NT       = K_DIM / BK;         // 32 k-tiles per pass
constexpr int NPASS    = C_DIM / 128;        // 4 n-chunk passes

// ---------------- EMA scan config ----------------
constexpr int EMA_CHUNK  = 128;
constexpr int EMA_WARMUP = 512;   // 0.95^512 ~ 4e-12 << fp32 ulp -> truncation exact

// ============================================================
// helpers
// ============================================================
__device__ __forceinline__ void cp_async16(void* smem_dst, const void* gmem_src) {
    uint32_t s = (uint32_t)__cvta_generic_to_shared(smem_dst);
    asm volatile("cp.async.cg.shared.global [%0], [%1], 16;\n" :: "r"(s), "l"(gmem_src));
}
__device__ __forceinline__ void cp_commit() {
    asm volatile("cp.async.commit_group;\n");
}
template <int N>
__device__ __forceinline__ void cp_wait() {
    asm volatile("cp.async.wait_group %0;\n" :: "n"(N));
}
__device__ __forceinline__ uint32_t f2tf32(float x) {   // round-to-nearest tf32 (same as wmma __float_to_tf32)
    uint32_t u; asm("cvt.rna.tf32.f32 %0, %1;" : "=r"(u) : "f"(x)); return u;
}
__device__ __forceinline__ void mma_tf32(float* c, const uint32_t* a, const uint32_t* b) {
    asm volatile(
        "mma.sync.aligned.m16n8k8.row.col.f32.tf32.tf32.f32 "
        "{%0,%1,%2,%3}, {%4,%5,%6,%7}, {%8,%9}, {%0,%1,%2,%3};\n"
        : "+f"(c[0]), "+f"(c[1]), "+f"(c[2]), "+f"(c[3])
        : "r"(a[0]), "r"(a[1]), "r"(a[2]), "r"(a[3]), "r"(b[0]), "r"(b[1]));
}

// ============================================================
// Kernel 1: EMA target via warmup-truncated parallel scan.
// ema_i = 0.05*g_i + 0.95*ema_{i-1};  greater = g_i > ema_i
// ============================================================
__global__ void ema_target_kernel(const float* __restrict__ rewards,
                                  float* __restrict__ target)
{
    int t = blockIdx.x * blockDim.x + threadIdx.x;   // 512 workers
    int start = t * EMA_CHUNK;
    if (start >= B_ROWS) return;
    int w0 = start - EMA_WARMUP;
    if (w0 < 0) w0 = 0;

    float ema = 0.0f;
    for (int i = w0; i < start; i++)
        ema = 0.05f * rewards[i] + 0.95f * ema;
    for (int i = start; i < start + EMA_CHUNK; i++) {
        float g = rewards[i];
        ema = 0.05f * g + 0.95f * ema;
        bool gt = g > ema;
        target[2 * i + 0] = gt ? 1.0f : 0.0f;
        target[2 * i + 1] = gt ? 0.0f : 1.0f;
    }
}

// ============================================================
// Kernel 2: fully-fused. Per block: h = relu(A_slab @ W^T + b), blend with
// prev, write comp, full-row wager GEMV reduced in smem (NO global atomics,
// NO init kernel). 4 passes over N; 2-stage cp.async ring per pass.
// Conflict-free manual fragment loads (LDS_R=20), mma.m16n8k8.tf32.
// ============================================================
__global__ __launch_bounds__(256, 2)
void fused_kernel(const float* __restrict__ A,
                  const float* __restrict__ prev,
                  const float* __restrict__ cascade,
                  const float* __restrict__ W,
                  const float* __restrict__ bias,
                  const float* __restrict__ Wwag,
                  const float* __restrict__ bwag,
                  float* __restrict__ wager,
                  float* __restrict__ comp)
{
    __shared__ float smem[SMEM_F];
    float* sbias = smem + AUX_OFF;
    float* swag0 = sbias + 512;
    float* swag1 = swag0 + 512;
    float* wacc  = swag1 + 512;     // 128 rows x 2

    const int t   = threadIdx.x;
    const int m0  = blockIdx.x * 128;
    const int w   = t >> 5;
    const int wm  = w >> 2;         // 0..1
    const int wn  = w & 3;          // 0..3
    const int lane = t & 31;
    const int g    = lane >> 2;     // 0..7
    const int tig  = lane & 3;      // 0..3

    // stage fill: thread t owns one smem row (A row t, or B row t-128), 4 x 16B
    auto issue_stage = [&](int s, int p, int kt) {
        float* drow = smem + s * STAGE_F + t * LDS_R;
        const float* srow = (t < 128)
            ? (A + (size_t)(m0 + t) * K_DIM + kt * BK)
            : (W + (size_t)(p * 128 + (t - 128)) * K_DIM + kt * BK);
        cp_async16(drow + 0,  srow + 0);
        cp_async16(drow + 4,  srow + 4);
        cp_async16(drow + 8,  srow + 8);
        cp_async16(drow + 12, srow + 12);
        cp_commit();
    };

    // get pass-0 tile-0 moving before anything else
    issue_stage(0, 0, 0);

    // aux loads + wager accumulator zero (visibility covered by mainloop barrier)
    for (int i = t; i < 512; i += 256) {
        sbias[i] = bias[i];
        swag0[i] = Wwag[i];
        swag1[i] = Wwag[C_DIM + i];
    }
    wacc[t] = 0.0f;   // 256 entries, 256 threads

    const float r   = *cascade;
    const float omr = 1.0f - r;

    for (int p = 0; p < NPASS; p++) {
        float acc[4][4][4];
#pragma unroll
        for (int mf = 0; mf < 4; mf++)
#pragma unroll
            for (int nf = 0; nf < 4; nf++)
#pragma unroll
                for (int e = 0; e < 4; e++)
                    acc[mf][nf][e] = 0.0f;

        if (p > 0) issue_stage(0, p, 0);   // stage0 free: all threads passed last tile's barrier

        for (int kt = 0; kt < NT; kt++) {
            cp_wait<0>();
            __syncthreads();               // tile kt visible to all; other stage fully consumed
            if (kt + 1 < NT) issue_stage((kt + 1) & 1, p, kt + 1);

            const float* st = smem + (kt & 1) * STAGE_F;
#pragma unroll
            for (int kk = 0; kk < 2; kk++) {
                const int ko = kk * 8;
                uint32_t af[4][4], bf[4][2];
#pragma unroll
                for (int mf = 0; mf < 4; mf++) {
                    const float* ar = st + (wm * 64 + mf * 16 + g) * LDS_R + ko;
                    af[mf][0] = f2tf32(ar[tig]);
                    af[mf][1] = f2tf32(ar[8 * LDS_R + tig]);
                    af[mf][2] = f2tf32(ar[tig + 4]);
                    af[mf][3] = f2tf32(ar[8 * LDS_R + tig + 4]);
                }
#pragma unroll
                for (int nf = 0; nf < 4; nf++) {
                    const float* br = st + (128 + wn * 32 + nf * 8 + g) * LDS_R + ko;
                    bf[nf][0] = f2tf32(br[tig]);
                    bf[nf][1] = f2tf32(br[tig + 4]);
                }
#pragma unroll
                for (int mf = 0; mf < 4; mf++)
#pragma unroll
                    for (int nf = 0; nf < 4; nf++)
                        mma_tf32(acc[mf][nf], af[mf], bf[nf]);
            }
        }

        // ---- pass epilogue: straight from registers (known c-frag layout) ----
        // c0:(g,2tig) c1:(g,2tig+1) c2:(g+8,2tig) c3:(g+8,2tig+1)
#pragma unroll
        for (int mf = 0; mf < 4; mf++) {
#pragma unroll
            for (int half = 0; half < 2; half++) {
                const int lr = wm * 64 + mf * 16 + g + half * 8;   // local row
                const size_t gr = (size_t)(m0 + lr);
                float wp0 = 0.0f, wp1 = 0.0f;
#pragma unroll
                for (int nf = 0; nf < 4; nf++) {
                    const int lc = p * 128 + wn * 32 + nf * 8 + 2 * tig;  // global col
                    const float c0 = acc[mf][nf][half * 2 + 0];
                    const float c1 = acc[mf][nf][half * 2 + 1];
                    const float2 pv = *reinterpret_cast<const float2*>(
                        prev + gr * C_DIM + lc);
                    const float h0 = fmaxf(c0 + sbias[lc],     0.0f);
                    const float h1 = fmaxf(c1 + sbias[lc + 1], 0.0f);
                    float2 o;
                    o.x = fmaf(r, h0, omr * pv.x);
                    o.y = fmaf(r, h1, omr * pv.y);
                    *reinterpret_cast<float2*>(comp + gr * C_DIM + lc) = o;
                    wp0 += o.x * swag0[lc] + o.y * swag0[lc + 1];
                    wp1 += o.x * swag1[lc] + o.y * swag1[lc + 1];
                }
                atomicAdd(&wacc[lr * 2 + 0], wp0);   // smem atomics, spread banks
                atomicAdd(&wacc[lr * 2 + 1], wp1);
            }
        }
    }

    __syncthreads();   // all wacc contributions visible
    if (t < 128) {
        const size_t gr = (size_t)(m0 + t);
        wager[gr * 2 + 0] = wacc[t * 2 + 0] + bwag[0];
        wager[gr * 2 + 1] = wacc[t * 2 + 1] + bwag[1];
    }
}

// ============================================================
// Launch — two launches, no statics, no attributes, no allocs.
// Inputs (metadata order):
//  0 comparison_matrix [B,512] f32   1 prev_comparison [B,512] f32
//  2 cascade_rate [1] f32            3 rewards [B] f32
//  4 W_comp [512,512] f32            5 b_comp [512] f32
//  6 W_wager [2,512] f32             7 b_wager [2] f32
// Output: concat( wager [B,2], comparison_out [B,512], target [B,2] ) f32
// ============================================================
extern "C" void kernel_launch(void* const* d_in, const int* in_sizes, int n_in,
                              void* d_out, int out_size)
{
    const float* A    = (const float*)d_in[0];
    const float* prev = (const float*)d_in[1];
    const float* casc = (const float*)d_in[2];
    const float* rew  = (const float*)d_in[3];
    const float* W    = (const float*)d_in[4];
    const float* bc   = (const float*)d_in[5];
    const float* Ww   = (const float*)d_in[6];
    const float* bw   = (const float*)d_in[7];

    float* out    = (float*)d_out;
    float* wager  = out;                                                // [B,2]
    float* comp   = out + (size_t)B_ROWS * 2;                           // [B,512]
    float* target = out + (size_t)B_ROWS * 2 + (size_t)B_ROWS * C_DIM;  // [B,2]

    ema_target_kernel<<<4, 128>>>(rew, target);
    fused_kernel<<<B_ROWS / 128, 256>>>(A, prev, casc, W, bc, Ww, bw, wager, comp);
}

// round 8
// speedup vs baseline: 1.2228x; 1.1278x over previous
#include <cuda_runtime.h>
#include <cstdint>
#include <cstddef>

// Problem dims (fixed by the dataset)
#define B_ROWS 65536
#define C_DIM  512
#define K_DIM  512

// ---------------- tiling ----------------
// grid = 512 blocks, each owns 128 rows x FULL N=512 (8 passes of 64 cols).
// block = 256 threads = 8 warps: wm in {0..3}, wn in {0,1}; warp tile 32x32
// = 2 m-frags (m16) x 4 n-frags (n8), mma.m16n8k8.tf32.
constexpr int BM = 128, BN = 64, BK = 16;
constexpr int LDS_R      = 20;                  // smem row stride (20g+tig covers all 32 banks)
constexpr int STAGE_ROWS = BM + BN;             // 192
constexpr int STAGE_F    = STAGE_ROWS * LDS_R;  // 3840 floats = 15360 B
constexpr int NSTAGE     = 3;
constexpr int WACC_OFF   = NSTAGE * STAGE_F;    // 11520
constexpr int SMEM_F     = WACC_OFF + 2 * BM;   // 11776 floats = 47104 B static (<48KB)
constexpr int NT         = K_DIM / BK;          // 32 k-tiles per pass
constexpr int NPASS      = C_DIM / BN;          // 8
constexpr int FT_TOT     = NT * NPASS;          // 256 flat tiles

// ---------------- EMA scan config ----------------
constexpr int EMA_CHUNK  = 128;
constexpr int EMA_WARMUP = 512;   // 0.95^512 ~ 4e-12 << fp32 ulp -> truncation exact

// ============================================================
// helpers
// ============================================================
__device__ __forceinline__ void cp_async16(void* smem_dst, const void* gmem_src) {
    uint32_t s = (uint32_t)__cvta_generic_to_shared(smem_dst);
    asm volatile("cp.async.cg.shared.global [%0], [%1], 16;\n" :: "r"(s), "l"(gmem_src));
}
__device__ __forceinline__ void cp_commit() {
    asm volatile("cp.async.commit_group;\n");
}
template <int N>
__device__ __forceinline__ void cp_wait() {
    asm volatile("cp.async.wait_group %0;\n" :: "n"(N));
}
__device__ __forceinline__ uint32_t f2tf32(float x) {   // round-to-nearest tf32
    uint32_t u; asm("cvt.rna.tf32.f32 %0, %1;" : "=r"(u) : "f"(x)); return u;
}
__device__ __forceinline__ void mma_tf32(float* c, const uint32_t* a, const uint32_t* b) {
    asm volatile(
        "mma.sync.aligned.m16n8k8.row.col.f32.tf32.tf32.f32 "
        "{%0,%1,%2,%3}, {%4,%5,%6,%7}, {%8,%9}, {%0,%1,%2,%3};\n"
        : "+f"(c[0]), "+f"(c[1]), "+f"(c[2]), "+f"(c[3])
        : "r"(a[0]), "r"(a[1]), "r"(a[2]), "r"(a[3]), "r"(b[0]), "r"(b[1]));
}

// ============================================================
// Kernel 1: EMA target via warmup-truncated parallel scan.
// ============================================================
__global__ void ema_target_kernel(const float* __restrict__ rewards,
                                  float* __restrict__ target)
{
    int t = blockIdx.x * blockDim.x + threadIdx.x;   // 512 workers
    int start = t * EMA_CHUNK;
    if (start >= B_ROWS) return;
    int w0 = start - EMA_WARMUP;
    if (w0 < 0) w0 = 0;

    float ema = 0.0f;
    for (int i = w0; i < start; i++)
        ema = 0.05f * rewards[i] + 0.95f * ema;
    for (int i = start; i < start + EMA_CHUNK; i++) {
        float g = rewards[i];
        ema = 0.05f * g + 0.95f * ema;
        bool gt = g > ema;
        target[2 * i + 0] = gt ? 1.0f : 0.0f;
        target[2 * i + 1] = gt ? 0.0f : 1.0f;
    }
}

// ============================================================
// Kernel 2: fused GEMM + relu + blend + wager GEMV.
// 3-stage cp.async ring over 256 flat (pass, k) tiles, cp_wait<1> (2-tile
// prefetch window). Conflict-free scalar fragment loads (LDS_R=20).
// Epilogue reads bias/W_wager straight from cached gmem (no smem aux).
// ============================================================
__global__ __launch_bounds__(256, 3)
void fused_kernel(const float* __restrict__ A,
                  const float* __restrict__ prev,
                  const float* __restrict__ cascade,
                  const float* __restrict__ W,
                  const float* __restrict__ bias,
                  const float* __restrict__ Wwag,
                  const float* __restrict__ bwag,
                  float* __restrict__ wager,
                  float* __restrict__ comp)
{
    __shared__ float smem[SMEM_F];
    float* wacc = smem + WACC_OFF;   // 128 rows x 2

    const int t    = threadIdx.x;
    const int m0   = blockIdx.x * BM;
    const int w    = t >> 5;
    const int wm   = w >> 1;        // 0..3
    const int wn   = w & 1;         // 0..1
    const int lane = t & 31;
    const int g    = lane >> 2;     // 0..7
    const int tig  = lane & 3;      // 0..3

    // stage fill: 192 rows x 4 x 16B = 768 chunks, 3 per thread
    auto issue_ft = [&](int ft, int s) {
        const int p  = ft >> 5;
        const int kt = ft & 31;
        float* st = smem + s * STAGE_F;
#pragma unroll
        for (int i = 0; i < 3; i++) {
            int c   = t + 256 * i;      // 0..767
            int row = c >> 2;
            int q   = (c & 3) * 4;
            const float* src = (row < BM)
                ? (A + (size_t)(m0 + row) * K_DIM + kt * BK + q)
                : (W + (size_t)(p * BN + (row - BM)) * K_DIM + kt * BK + q);
            cp_async16(st + row * LDS_R + q, src);
        }
        cp_commit();
    };

    issue_ft(0, 0);
    issue_ft(1, 1);
    wacc[t] = 0.0f;   // 256 entries, 256 threads (visible by first mainloop barrier)

    const float r   = *cascade;
    const float omr = 1.0f - r;

    float acc[2][4][4];
#pragma unroll
    for (int mf = 0; mf < 2; mf++)
#pragma unroll
        for (int nf = 0; nf < 4; nf++)
#pragma unroll
            for (int e = 0; e < 4; e++)
                acc[mf][nf][e] = 0.0f;

    int scur = 0;   // stage of flat-tile ft; (scur+2)%3 is the reissue target
    for (int ft = 0; ft < FT_TOT; ft++) {
        cp_wait<1>();
        __syncthreads();             // tile ft visible everywhere; stage (ft-1)%3 fully consumed

        if (ft + 2 < FT_TOT) {
            int snx = scur + 2; if (snx >= 3) snx -= 3;
            issue_ft(ft + 2, snx);
        }

        const float* st = smem + scur * STAGE_F;
#pragma unroll
        for (int kk = 0; kk < 2; kk++) {
            const int ko = kk * 8;
            uint32_t af[2][4], bf[4][2];
#pragma unroll
            for (int mf = 0; mf < 2; mf++) {
                const float* ar = st + (wm * 32 + mf * 16 + g) * LDS_R + ko;
                af[mf][0] = f2tf32(ar[tig]);
                af[mf][1] = f2tf32(ar[8 * LDS_R + tig]);
                af[mf][2] = f2tf32(ar[tig + 4]);
                af[mf][3] = f2tf32(ar[8 * LDS_R + tig + 4]);
            }
#pragma unroll
            for (int nf = 0; nf < 4; nf++) {
                const float* br = st + (BM + wn * 32 + nf * 8 + g) * LDS_R + ko;
                bf[nf][0] = f2tf32(br[tig]);
                bf[nf][1] = f2tf32(br[tig + 4]);
            }
#pragma unroll
            for (int mf = 0; mf < 2; mf++)
#pragma unroll
                for (int nf = 0; nf < 4; nf++)
                    mma_tf32(acc[mf][nf], af[mf], bf[nf]);
        }

        // ---- pass epilogue (kt == 31): registers -> gmem, no barrier needed ----
        if ((ft & 31) == 31) {
            const int p = ft >> 5;
#pragma unroll
            for (int mf = 0; mf < 2; mf++) {
#pragma unroll
                for (int half = 0; half < 2; half++) {
                    const int lr = wm * 32 + mf * 16 + g + half * 8;
                    const size_t gr = (size_t)(m0 + lr);
                    float wp0 = 0.0f, wp1 = 0.0f;
#pragma unroll
                    for (int nf = 0; nf < 4; nf++) {
                        const int lc = p * BN + wn * 32 + nf * 8 + 2 * tig;
                        const float c0 = acc[mf][nf][half * 2 + 0];
                        const float c1 = acc[mf][nf][half * 2 + 1];
                        const float2 bv = *reinterpret_cast<const float2*>(bias + lc);
                        const float2 pv = *reinterpret_cast<const float2*>(
                            prev + gr * C_DIM + lc);
                        const float h0 = fmaxf(c0 + bv.x, 0.0f);
                        const float h1 = fmaxf(c1 + bv.y, 0.0f);
                        float2 o;
                        o.x = fmaf(r, h0, omr * pv.x);
                        o.y = fmaf(r, h1, omr * pv.y);
                        *reinterpret_cast<float2*>(comp + gr * C_DIM + lc) = o;
                        const float2 w0v = *reinterpret_cast<const float2*>(Wwag + lc);
                        const float2 w1v = *reinterpret_cast<const float2*>(Wwag + C_DIM + lc);
                        wp0 += o.x * w0v.x + o.y * w0v.y;
                        wp1 += o.x * w1v.x + o.y * w1v.y;
                    }
                    atomicAdd(&wacc[lr * 2 + 0], wp0);
                    atomicAdd(&wacc[lr * 2 + 1], wp1);
                }
            }
#pragma unroll
            for (int mf = 0; mf < 2; mf++)
#pragma unroll
                for (int nf = 0; nf < 4; nf++)
#pragma unroll
                    for (int e = 0; e < 4; e++)
                        acc[mf][nf][e] = 0.0f;
        }

        if (++scur == 3) scur = 0;
    }

    __syncthreads();   // all wacc contributions visible
    if (t < BM) {
        const size_t gr = (size_t)(m0 + t);
        wager[gr * 2 + 0] = wacc[t * 2 + 0] + bwag[0];
        wager[gr * 2 + 1] = wacc[t * 2 + 1] + bwag[1];
    }
}

// ============================================================
// Launch — two launches, no statics, no attributes, no allocs.
// Inputs (metadata order):
//  0 comparison_matrix [B,512] f32   1 prev_comparison [B,512] f32
//  2 cascade_rate [1] f32            3 rewards [B] f32
//  4 W_comp [512,512] f32            5 b_comp [512] f32
//  6 W_wager [2,512] f32             7 b_wager [2] f32
// Output: concat( wager [B,2], comparison_out [B,512], target [B,2] ) f32
// ============================================================
extern "C" void kernel_launch(void* const* d_in, const int* in_sizes, int n_in,
                              void* d_out, int out_size)
{
    const float* A    = (const float*)d_in[0];
    const float* prev = (const float*)d_in[1];
    const float* casc = (const float*)d_in[2];
    const float* rew  = (const float*)d_in[3];
    const float* W    = (const float*)d_in[4];
    const float* bc   = (const float*)d_in[5];
    const float* Ww   = (const float*)d_in[6];
    const float* bw   = (const float*)d_in[7];

    float* out    = (float*)d_out;
    float* wager  = out;                                                // [B,2]
    float* comp   = out + (size_t)B_ROWS * 2;                           // [B,512]
    float* target = out + (size_t)B_ROWS * 2 + (size_t)B_ROWS * C_DIM;  // [B,2]

    ema_target_kernel<<<4, 128>>>(rew, target);
    fused_kernel<<<B_ROWS / BM, 256>>>(A, prev, casc, W, bc, Ww, bw, wager, comp);
}